// round 13
// baseline (speedup 1.0000x reference)
#include <cuda_runtime.h>
#include <cuda_fp16.h>
#include <cstdint>

// Problem constants
#define BB 4
#define SS 2048
#define DD 1024
#define OO 1024
#define EE 16
#define KK 512

// GEMM tiling (HMMA mma.sync path, baseline sm_100 ISA)
#define BM 128
#define BN 128
#define BK 64
#define NCH 16                     // 1024 / 64 k-chunks
#define STG 3
#define A_TILE 16384               // 128 x 64 halves
#define B_TILE 16384               // 64 x 128 halves (two 64x64 SW128 blocks)
#define STAGE_BYTES (A_TILE + B_TILE)        // 32768
#define SMEM_DYN (STAGE_BYTES * STG)         // 98304

#define GATE_BLOCKS (BB * SS / 8)            // 1024 (8 tokens per block)
#define WCONV_BLOCKS (EE * 8 * NCH)          // 2048

// ---------------- device scratch ----------------
__device__ float g_logits[BB * EE * SS];
__device__ int   g_idx  [BB * EE * KK];
__device__ float g_inv  [BB * EE * KK];
// fp16 image of x, [b][s][d] (16 MB) — GEMM gathers A rows directly from here
__device__ __align__(1024) __half g_xh[(size_t)BB * SS * DD];
// B images: [e(16)][nt(8)][kc(16)] tiles: [h=2][k=64][n=64] halves, SW128  (32 MB)
__device__ __align__(1024) unsigned char g_wt[16u * 8u * 16u * B_TILE];

// ---------------- PTX helpers (baseline ISA only) ----------------
__device__ __forceinline__ uint32_t smem_u32(const void* p) {
    uint32_t a;
    asm("{ .reg .u64 t; cvta.to.shared.u64 t, %1; cvt.u32.u64 %0, t; }" : "=r"(a) : "l"(p));
    return a;
}
__device__ __forceinline__ void cp16(uint32_t dst, const void* src) {
    asm volatile("cp.async.cg.shared.global [%0], [%1], 16;" :: "r"(dst), "l"(src) : "memory");
}
__device__ __forceinline__ void cp_commit() {
    asm volatile("cp.async.commit_group;" ::: "memory");
}
template <int N> __device__ __forceinline__ void cp_wait() {
    asm volatile("cp.async.wait_group %0;" :: "n"(N) : "memory");
}
__device__ __forceinline__ void ldsm_x4(uint32_t* r, uint32_t addr) {
    asm volatile("ldmatrix.sync.aligned.m8n8.x4.shared.b16 {%0,%1,%2,%3}, [%4];"
        : "=r"(r[0]), "=r"(r[1]), "=r"(r[2]), "=r"(r[3]) : "r"(addr));
}
__device__ __forceinline__ void ldsm_x4_t(uint32_t* r, uint32_t addr) {
    asm volatile("ldmatrix.sync.aligned.m8n8.x4.trans.shared.b16 {%0,%1,%2,%3}, [%4];"
        : "=r"(r[0]), "=r"(r[1]), "=r"(r[2]), "=r"(r[3]) : "r"(addr));
}
__device__ __forceinline__ void mma16816(float* c, const uint32_t* a, uint32_t b0, uint32_t b1) {
    asm volatile(
        "mma.sync.aligned.m16n8k16.row.col.f32.f16.f16.f32 "
        "{%0,%1,%2,%3}, {%4,%5,%6,%7}, {%8,%9}, {%0,%1,%2,%3};"
        : "+f"(c[0]), "+f"(c[1]), "+f"(c[2]), "+f"(c[3])
        : "r"(a[0]), "r"(a[1]), "r"(a[2]), "r"(a[3]), "r"(b0), "r"(b1));
}
__device__ __forceinline__ void red2(float* ptr, float a, float b) {
    asm volatile("red.global.add.v2.f32 [%0], {%1, %2};"
        :: "l"(ptr), "f"(a), "f"(b) : "memory");
}
__device__ __forceinline__ int swz(int off) { return off ^ ((off >> 3) & 0x70); }

// ============================================================================
// Kernel 1 (fused prep):
//   blocks [0, 1024): gate for 8 tokens (warp/token, d-sliced outer product,
//                     coalesced 64B gw rows) + zero 8 out rows + fp16 x image.
//   blocks [1024, 3072): convert W -> pre-swizzled fp16 B-tile images.
// ============================================================================
__global__ __launch_bounds__(256) void prep_kernel(
    const float* __restrict__ x, const float* __restrict__ gw,
    const float* __restrict__ gb, const float* __restrict__ w,
    float* __restrict__ out)
{
    if (blockIdx.x < GATE_BLOCKS) {
        int bs0 = blockIdx.x * 8;

        float4* oz = (float4*)(out + (size_t)bs0 * OO);   // zero 8 rows
        #pragma unroll
        for (int q = 0; q < 8; q++)
            oz[q * 256 + threadIdx.x] = make_float4(0.f, 0.f, 0.f, 0.f);

        __shared__ float sx[8 * DD];                      // 32 KB
        const float4* xr = (const float4*)(x + (size_t)bs0 * DD);
        #pragma unroll
        for (int q = 0; q < 8; q++)
            ((float4*)sx)[q * 256 + threadIdx.x] = xr[q * 256 + threadIdx.x];
        __syncthreads();

        // fp16 x image: 8 tokens * 512 half2 = 4096 uint32, 16 per thread
        uint32_t* xh = (uint32_t*)(g_xh + (size_t)bs0 * DD);
        #pragma unroll
        for (int j = 0; j < 16; j++) {
            int idx = j * 256 + threadIdx.x;              // 0..4095 half2-slots
            __half2 h = __floats2half2_rn(sx[idx * 2], sx[idx * 2 + 1]);
            xh[idx] = *(uint32_t*)&h;
        }

        int wp = threadIdx.x >> 5, l = threadIdx.x & 31;
        int bs = bs0 + wp;
        int b  = bs >> 11, s = bs & (SS - 1);
        const float* xw = sx + wp * DD;

        // d-sliced outer product: lane owns d = l + 32*it; 16 independent
        // per-expert accumulators; gw row [d][0..15] = 64B contiguous.
        float acc[16];
        #pragma unroll
        for (int e = 0; e < 16; e++) acc[e] = 0.0f;
        #pragma unroll 4
        for (int it = 0; it < 32; it++) {
            int d = it * 32 + l;
            float xv = xw[d];
            const float4* g4 = (const float4*)(gw + (size_t)d * EE);
            float4 g0 = g4[0], g1 = g4[1], g2 = g4[2], g3 = g4[3];
            acc[0]  += xv * g0.x; acc[1]  += xv * g0.y;
            acc[2]  += xv * g0.z; acc[3]  += xv * g0.w;
            acc[4]  += xv * g1.x; acc[5]  += xv * g1.y;
            acc[6]  += xv * g1.z; acc[7]  += xv * g1.w;
            acc[8]  += xv * g2.x; acc[9]  += xv * g2.y;
            acc[10] += xv * g2.z; acc[11] += xv * g2.w;
            acc[12] += xv * g3.x; acc[13] += xv * g3.y;
            acc[14] += xv * g3.z; acc[15] += xv * g3.w;
        }
        // Reduce each expert across the warp; lane e keeps expert e (static idx).
        float res = 0.0f;
        #pragma unroll
        for (int e = 0; e < 16; e++) {
            float v = acc[e];
            #pragma unroll
            for (int off = 16; off > 0; off >>= 1)
                v += __shfl_xor_sync(0xffffffffu, v, off);
            if (l == e) res = v;
        }
        if (l < 16)
            g_logits[((size_t)(b * EE + l)) * SS + s] = res + gb[l];
    } else {
        // ---- W conversion ----
        int blk = blockIdx.x - GATE_BLOCKS;
        int kc = blk & 15, nt = (blk >> 4) & 7, e = blk >> 7;
        const float* src = w + ((size_t)e * DD + kc * 64) * OO + (size_t)nt * 128;
        unsigned char* tile = g_wt + (size_t)blk * B_TILE;

        #pragma unroll
        for (int it = 0; it < 4; it++) {
            int u = it * 256 + threadIdx.x;      // 0..1023 : k(64) x c16(16)
            int k = u >> 4, c16 = u & 15;
            const float4* sp = (const float4*)(src + (size_t)k * OO + c16 * 8);
            float4 a = sp[0], c = sp[1];
            __half2 h0 = __floats2half2_rn(a.x, a.y);
            __half2 h1 = __floats2half2_rn(a.z, a.w);
            __half2 h2 = __floats2half2_rn(c.x, c.y);
            __half2 h3 = __floats2half2_rn(c.z, c.w);
            uint4 v;
            v.x = *(uint32_t*)&h0; v.y = *(uint32_t*)&h1;
            v.z = *(uint32_t*)&h2; v.w = *(uint32_t*)&h3;
            int h = c16 >> 3;
            *(uint4*)(tile + h * 8192 + swz(k * 128 + (c16 & 7) * 16)) = v;
        }
    }
}

// ============================================================================
// Kernel 2: softmax stats + exact top-K via bitonic sort per (b,e)
// ============================================================================
__global__ __launch_bounds__(1024) void topk_kernel()
{
    int be = blockIdx.x;
    int t  = threadIdx.x;
    __shared__ float sv[2048];
    __shared__ int   si[2048];
    __shared__ float red[1024];

    const float* lp = g_logits + (size_t)be * SS;
    sv[t] = lp[t]; sv[t + 1024] = lp[t + 1024];
    si[t] = t;     si[t + 1024] = t + 1024;
    __syncthreads();

    float m = fmaxf(sv[t], sv[t + 1024]);
    red[t] = m; __syncthreads();
    for (int s2 = 512; s2 > 0; s2 >>= 1) { if (t < s2) red[t] = fmaxf(red[t], red[t + s2]); __syncthreads(); }
    float gmax = red[0]; __syncthreads();

    float se = expf(sv[t] - gmax) + expf(sv[t + 1024] - gmax);
    red[t] = se; __syncthreads();
    for (int s2 = 512; s2 > 0; s2 >>= 1) { if (t < s2) red[t] += red[t + s2]; __syncthreads(); }
    float gsum = red[0]; __syncthreads();

    for (int k = 2; k <= 2048; k <<= 1) {
        for (int j = k >> 1; j > 0; j >>= 1) {
            #pragma unroll 1
            for (int base = 0; base < 2048; base += 1024) {
                int i = base + t, ixj = i ^ j;
                if (ixj > i) {
                    float vi = sv[i], vj = sv[ixj];
                    int   ii = si[i], ij = si[ixj];
                    bool good = (vi > vj) || (vi == vj && ii < ij);
                    bool dir  = ((i & k) == 0);
                    if (dir ? (!good) : good) {
                        sv[i] = vj; sv[ixj] = vi;
                        si[i] = ij; si[ixj] = ii;
                    }
                }
            }
            __syncthreads();
        }
    }
    if (t < KK) {
        g_idx[(size_t)be * KK + t] = si[t];
        g_inv[(size_t)be * KK + t] = gsum * expf(gmax - sv[t]);
    }
}

// ============================================================================
// Kernel 3: HMMA GEMM, A gathered from g_xh via REGISTER-HELD row offsets
// grid = (nt=8, mt=4, be=64); 256 threads = 8 warps in 4(m) x 2(n); 2 CTAs/SM
// ============================================================================
__global__ __launch_bounds__(256, 2) void gemm_kernel(
    const float* __restrict__ bias, float* __restrict__ out)
{
    extern __shared__ unsigned char smem[];
    __shared__ int stok[BM];
    uint32_t sbase = smem_u32(smem);

    int tid = threadIdx.x, wid = tid >> 5, lane = tid & 31;
    int nt = blockIdx.x, mt = blockIdx.y, be = blockIdx.z;
    int b = be >> 4, e = be & 15;

    if (tid < BM) stok[tid] = g_idx[(size_t)be * KK + mt * BM + tid];
    __syncthreads();

    const char* Axh = (const char*)(g_xh + (size_t)b * SS * DD);
    const unsigned char* Bbase = g_wt + ((size_t)(e * 8 + nt) * NCH) * B_TILE;

    // --- A-gather addressing, fully precomputed (no smem/IMAD in the loop) ---
    uint32_t arow[4];
    #pragma unroll
    for (int q = 0; q < 4; q++)
        arow[q] = (uint32_t)stok[(tid >> 3) + q * 32] * (DD * 2) + (tid & 7) * 16;
    uint32_t sdstA = swz(tid * 16);

    int warp_m = wid >> 1, warp_n = wid & 1;
    int m_w = warp_m * 32, n_w = warp_n * 64;

    // Compact ldmatrix offsets: swz(off + v*32) == swz(off) ^ (v<<5)
    uint32_t offA[2];
    #pragma unroll
    for (int mi = 0; mi < 2; mi++)
        offA[mi] = swz((m_w + mi * 16 + (lane & 15)) * 128 + (lane >> 4) * 16);
    uint32_t offB[4];
    #pragma unroll
    for (int ks = 0; ks < 4; ks++)
        offB[ks] = (uint32_t)(A_TILE + warp_n * 8192 +
                   swz((ks * 16 + (lane & 15)) * 128 + (lane >> 4) * 16));

    float c[2][8][4];
    #pragma unroll
    for (int mi = 0; mi < 2; mi++)
        #pragma unroll
        for (int nj = 0; nj < 8; nj++)
            #pragma unroll
            for (int q = 0; q < 4; q++) c[mi][nj][q] = 0.0f;

    // stage loader: 8 cp16 with register addressing only
    auto load_stage = [&](int ch, int st) {
        uint32_t dst = sbase + st * STAGE_BYTES;
        const char* Ax = Axh + ch * 128;                    // ch*64 halves
        #pragma unroll
        for (int q = 0; q < 4; q++)
            cp16(dst + sdstA + q * 4096, Ax + arow[q]);
        const unsigned char* Bs = Bbase + (size_t)ch * B_TILE + tid * 16;
        uint32_t bd = dst + A_TILE + tid * 16;
        #pragma unroll
        for (int q = 0; q < 4; q++)
            cp16(bd + q * 4096, Bs + q * 4096);
    };

    // prologue: stages 0..STG-2
    #pragma unroll
    for (int s = 0; s < STG - 1; s++) { load_stage(s, s); cp_commit(); }

    int st = 0;
    for (int i = 0; i < NCH; i++) {
        cp_wait<STG - 2>();
        __syncthreads();

        // Issue next chunk's copy BEFORE computing (target stage was consumed
        // in iteration i-1; the barrier above proves all threads are done).
        if (i + STG - 1 < NCH) {
            int nst = st + STG - 1; if (nst >= STG) nst -= STG;
            load_stage(i + STG - 1, nst);
        }
        cp_commit();

        uint32_t sb = sbase + st * STAGE_BYTES;
        #pragma unroll
        for (int ks = 0; ks < 4; ks++) {
            uint32_t a[2][4], bf[4][4];
            ldsm_x4(a[0], sb + (offA[0] ^ (ks << 5)));
            ldsm_x4(a[1], sb + (offA[1] ^ (ks << 5)));
            #pragma unroll
            for (int p = 0; p < 4; p++) ldsm_x4_t(bf[p], sb + (offB[ks] ^ (p << 5)));
            #pragma unroll
            for (int mi = 0; mi < 2; mi++)
                #pragma unroll
                for (int p = 0; p < 4; p++) {
                    mma16816(c[mi][2 * p],     a[mi], bf[p][0], bf[p][1]);
                    mma16816(c[mi][2 * p + 1], a[mi], bf[p][2], bf[p][3]);
                }
        }
        if (++st == STG) st = 0;
    }

    // -------- epilogue: (c + bias) * inv, red.v2 scatter-add by token --------
    float bi = bias[e];
    #pragma unroll
    for (int mi = 0; mi < 2; mi++) {
        #pragma unroll
        for (int r = 0; r < 2; r++) {
            int mrow = m_w + mi * 16 + r * 8 + (lane >> 2);
            int gm   = mt * 128 + mrow;
            int tok  = stok[mrow];
            float inv = g_inv[(size_t)be * KK + gm];
            float* orow = out + ((size_t)b * SS + tok) * OO + nt * 128 + n_w + (lane & 3) * 2;
            #pragma unroll
            for (int nj = 0; nj < 8; nj++)
                red2(&orow[nj * 8],
                     (c[mi][nj][r * 2]     + bi) * inv,
                     (c[mi][nj][r * 2 + 1] + bi) * inv);
        }
    }
}

// ============================================================================
// Launch: prep(1) -> topk(2) -> gemm(3)
// ============================================================================
extern "C" void kernel_launch(void* const* d_in, const int* in_sizes, int n_in,
                              void* d_out, int out_size)
{
    const float* x   = (const float*)d_in[0];   // [B,S,D]
    const float* gw  = (const float*)d_in[1];   // [D,E]
    const float* gb  = (const float*)d_in[2];   // [E]
    const float* w   = (const float*)d_in[3];   // [E,D,O]
    const float* bia = (const float*)d_in[4];   // [E,1]
    float* out = (float*)d_out;
    (void)in_sizes; (void)n_in; (void)out_size;

    cudaFuncSetAttribute(gemm_kernel, cudaFuncAttributeMaxDynamicSharedMemorySize, SMEM_DYN);

    prep_kernel<<<GATE_BLOCKS + WCONV_BLOCKS, 256>>>(x, gw, gb, w, out);
    topk_kernel<<<BB * EE, 1024>>>();
    {
        dim3 grid(OO / BN, KK / BM, BB * EE);   // (8, 4, 64)
        gemm_kernel<<<grid, 256, SMEM_DYN>>>(bia, out);
    }
}

// round 15
// speedup vs baseline: 1.0495x; 1.0495x over previous
#include <cuda_runtime.h>
#include <cuda_fp16.h>
#include <cstdint>

// Problem constants
#define BB 4
#define SS 2048
#define DD 1024
#define OO 1024
#define EE 16
#define KK 512

// GEMM tiling (HMMA mma.sync path, baseline sm_100 ISA)
#define BM 128
#define BN 128
#define BK 64
#define NCH 16                     // 1024 / 64 k-chunks
#define STG 3
#define A_TILE 16384               // 128 x 64 halves
#define B_TILE 16384               // 64 x 128 halves (two 64x64 SW128 blocks)
#define STAGE_BYTES (A_TILE + B_TILE)        // 32768
#define SMEM_DYN (STAGE_BYTES * STG)         // 98304

#define GATE_BLOCKS (BB * SS / 8)            // 1024 (8 tokens per block)
#define WCONV_BLOCKS (EE * 8 * NCH)          // 2048

// ---------------- device scratch ----------------
__device__ float g_logits[BB * EE * SS];
__device__ int   g_idx  [BB * EE * KK];
__device__ float g_inv  [BB * EE * KK];
// fp16 image of x, [b][s][d] (16 MB) — GEMM gathers A rows directly from here
__device__ __align__(1024) __half g_xh[(size_t)BB * SS * DD];
// B images: [e(16)][nt(8)][kc(16)] tiles: [h=2][k=64][n=64] halves, SW128  (32 MB)
__device__ __align__(1024) unsigned char g_wt[16u * 8u * 16u * B_TILE];

// ---------------- PTX helpers (baseline ISA only) ----------------
__device__ __forceinline__ uint32_t smem_u32(const void* p) {
    uint32_t a;
    asm("{ .reg .u64 t; cvta.to.shared.u64 t, %1; cvt.u32.u64 %0, t; }" : "=r"(a) : "l"(p));
    return a;
}
__device__ __forceinline__ void cp16(uint32_t dst, const void* src) {
    asm volatile("cp.async.cg.shared.global [%0], [%1], 16;" :: "r"(dst), "l"(src) : "memory");
}
__device__ __forceinline__ void cp_commit() {
    asm volatile("cp.async.commit_group;" ::: "memory");
}
template <int N> __device__ __forceinline__ void cp_wait() {
    asm volatile("cp.async.wait_group %0;" :: "n"(N) : "memory");
}
__device__ __forceinline__ void ldsm_x4(uint32_t* r, uint32_t addr) {
    asm volatile("ldmatrix.sync.aligned.m8n8.x4.shared.b16 {%0,%1,%2,%3}, [%4];"
        : "=r"(r[0]), "=r"(r[1]), "=r"(r[2]), "=r"(r[3]) : "r"(addr));
}
__device__ __forceinline__ void ldsm_x4_t(uint32_t* r, uint32_t addr) {
    asm volatile("ldmatrix.sync.aligned.m8n8.x4.trans.shared.b16 {%0,%1,%2,%3}, [%4];"
        : "=r"(r[0]), "=r"(r[1]), "=r"(r[2]), "=r"(r[3]) : "r"(addr));
}
__device__ __forceinline__ void mma16816(float* c, const uint32_t* a, uint32_t b0, uint32_t b1) {
    asm volatile(
        "mma.sync.aligned.m16n8k16.row.col.f32.f16.f16.f32 "
        "{%0,%1,%2,%3}, {%4,%5,%6,%7}, {%8,%9}, {%0,%1,%2,%3};"
        : "+f"(c[0]), "+f"(c[1]), "+f"(c[2]), "+f"(c[3])
        : "r"(a[0]), "r"(a[1]), "r"(a[2]), "r"(a[3]), "r"(b0), "r"(b1));
}
__device__ __forceinline__ void red2(float* ptr, float a, float b) {
    asm volatile("red.global.add.v2.f32 [%0], {%1, %2};"
        :: "l"(ptr), "f"(a), "f"(b) : "memory");
}
__device__ __forceinline__ int swz(int off) { return off ^ ((off >> 3) & 0x70); }

// ============================================================================
// Kernel 1 (fused prep):
//   blocks [0, 1024): gate for 8 tokens (warp/token, lane=(expert,d-parity),
//                     1-line-per-LDG coalescing, 4 independent FFMA chains)
//                     + zero 8 out rows + fp16 x image.
//   blocks [1024, 3072): convert W -> pre-swizzled fp16 B-tile images.
// ============================================================================
__global__ __launch_bounds__(256) void prep_kernel(
    const float* __restrict__ x, const float* __restrict__ gw,
    const float* __restrict__ gb, const float* __restrict__ w,
    float* __restrict__ out)
{
    if (blockIdx.x < GATE_BLOCKS) {
        int bs0 = blockIdx.x * 8;

        float4* oz = (float4*)(out + (size_t)bs0 * OO);   // zero 8 rows
        #pragma unroll
        for (int q = 0; q < 8; q++)
            oz[q * 256 + threadIdx.x] = make_float4(0.f, 0.f, 0.f, 0.f);

        __shared__ float sx[8 * DD];                      // 32 KB
        const float4* xr = (const float4*)(x + (size_t)bs0 * DD);
        #pragma unroll
        for (int q = 0; q < 8; q++)
            ((float4*)sx)[q * 256 + threadIdx.x] = xr[q * 256 + threadIdx.x];
        __syncthreads();

        // fp16 x image: 8 tokens * 512 half2 = 4096 uint32, 16 per thread
        uint32_t* xh = (uint32_t*)(g_xh + (size_t)bs0 * DD);
        #pragma unroll
        for (int j = 0; j < 16; j++) {
            int idx = j * 256 + threadIdx.x;              // 0..4095 half2-slots
            __half2 h = __floats2half2_rn(sx[idx * 2], sx[idx * 2 + 1]);
            xh[idx] = *(uint32_t*)&h;
        }

        int wp = threadIdx.x >> 5, l = threadIdx.x & 31;
        int e  = l & 15, dh = l >> 4;                     // expert, d-parity
        int bs = bs0 + wp;
        int b  = bs >> 11, s = bs & (SS - 1);
        const float* xw = sx + wp * DD;

        // Coalesced gw walk (warp covers rows d,d+1 x 16 experts = one 128B
        // line per LDG) with 4 independent accumulator chains for ILP.
        // k = it*4+j spans [0,512) -> d = dh + 2k covers the FULL 1024 dims.
        float acc[4];
        #pragma unroll
        for (int j = 0; j < 4; j++) acc[j] = 0.0f;
        #pragma unroll 2
        for (int it = 0; it < 128; it++) {
            #pragma unroll
            for (int j = 0; j < 4; j++) {
                int d = dh + (it * 4 + j) * 2;
                acc[j] += xw[d] * gw[d * EE + e];
            }
        }
        float a2 = (acc[0] + acc[2]) + (acc[1] + acc[3]);
        a2 += __shfl_xor_sync(0xffffffffu, a2, 16);       // even-d + odd-d halves
        if (l < 16)
            g_logits[((size_t)(b * EE + l)) * SS + s] = a2 + gb[l];
    } else {
        // ---- W conversion ----
        int blk = blockIdx.x - GATE_BLOCKS;
        int kc = blk & 15, nt = (blk >> 4) & 7, e = blk >> 7;
        const float* src = w + ((size_t)e * DD + kc * 64) * OO + (size_t)nt * 128;
        unsigned char* tile = g_wt + (size_t)blk * B_TILE;

        #pragma unroll
        for (int it = 0; it < 4; it++) {
            int u = it * 256 + threadIdx.x;      // 0..1023 : k(64) x c16(16)
            int k = u >> 4, c16 = u & 15;
            const float4* sp = (const float4*)(src + (size_t)k * OO + c16 * 8);
            float4 a = sp[0], c = sp[1];
            __half2 h0 = __floats2half2_rn(a.x, a.y);
            __half2 h1 = __floats2half2_rn(a.z, a.w);
            __half2 h2 = __floats2half2_rn(c.x, c.y);
            __half2 h3 = __floats2half2_rn(c.z, c.w);
            uint4 v;
            v.x = *(uint32_t*)&h0; v.y = *(uint32_t*)&h1;
            v.z = *(uint32_t*)&h2; v.w = *(uint32_t*)&h3;
            int h = c16 >> 3;
            *(uint4*)(tile + h * 8192 + swz(k * 128 + (c16 & 7) * 16)) = v;
        }
    }
}

// ============================================================================
// Kernel 2: softmax stats + exact top-K via bitonic sort per (b,e)
// ============================================================================
__global__ __launch_bounds__(1024) void topk_kernel()
{
    int be = blockIdx.x;
    int t  = threadIdx.x;
    __shared__ float sv[2048];
    __shared__ int   si[2048];
    __shared__ float red[1024];

    const float* lp = g_logits + (size_t)be * SS;
    sv[t] = lp[t]; sv[t + 1024] = lp[t + 1024];
    si[t] = t;     si[t + 1024] = t + 1024;
    __syncthreads();

    float m = fmaxf(sv[t], sv[t + 1024]);
    red[t] = m; __syncthreads();
    for (int s2 = 512; s2 > 0; s2 >>= 1) { if (t < s2) red[t] = fmaxf(red[t], red[t + s2]); __syncthreads(); }
    float gmax = red[0]; __syncthreads();

    float se = expf(sv[t] - gmax) + expf(sv[t + 1024] - gmax);
    red[t] = se; __syncthreads();
    for (int s2 = 512; s2 > 0; s2 >>= 1) { if (t < s2) red[t] += red[t + s2]; __syncthreads(); }
    float gsum = red[0]; __syncthreads();

    for (int k = 2; k <= 2048; k <<= 1) {
        for (int j = k >> 1; j > 0; j >>= 1) {
            #pragma unroll 1
            for (int base = 0; base < 2048; base += 1024) {
                int i = base + t, ixj = i ^ j;
                if (ixj > i) {
                    float vi = sv[i], vj = sv[ixj];
                    int   ii = si[i], ij = si[ixj];
                    bool good = (vi > vj) || (vi == vj && ii < ij);
                    bool dir  = ((i & k) == 0);
                    if (dir ? (!good) : good) {
                        sv[i] = vj; sv[ixj] = vi;
                        si[i] = ij; si[ixj] = ii;
                    }
                }
            }
            __syncthreads();
        }
    }
    if (t < KK) {
        g_idx[(size_t)be * KK + t] = si[t];
        g_inv[(size_t)be * KK + t] = gsum * expf(gmax - sv[t]);
    }
}

// ============================================================================
// Kernel 3: HMMA GEMM, A gathered from g_xh via REGISTER-HELD row offsets
// grid = (nt=8, mt=4, be=64); 256 threads = 8 warps in 4(m) x 2(n); 2 CTAs/SM
// ============================================================================
__global__ __launch_bounds__(256, 2) void gemm_kernel(
    const float* __restrict__ bias, float* __restrict__ out)
{
    extern __shared__ unsigned char smem[];
    __shared__ int stok[BM];
    uint32_t sbase = smem_u32(smem);

    int tid = threadIdx.x, wid = tid >> 5, lane = tid & 31;
    int nt = blockIdx.x, mt = blockIdx.y, be = blockIdx.z;
    int b = be >> 4, e = be & 15;

    if (tid < BM) stok[tid] = g_idx[(size_t)be * KK + mt * BM + tid];
    __syncthreads();

    const char* Axh = (const char*)(g_xh + (size_t)b * SS * DD);
    const unsigned char* Bbase = g_wt + ((size_t)(e * 8 + nt) * NCH) * B_TILE;

    // --- A-gather addressing, fully precomputed (no smem/IMAD in the loop) ---
    uint32_t arow[4];
    #pragma unroll
    for (int q = 0; q < 4; q++)
        arow[q] = (uint32_t)stok[(tid >> 3) + q * 32] * (DD * 2) + (tid & 7) * 16;
    uint32_t sdstA = swz(tid * 16);

    int warp_m = wid >> 1, warp_n = wid & 1;
    int m_w = warp_m * 32, n_w = warp_n * 64;

    // Compact ldmatrix offsets: swz(off + v*32) == swz(off) ^ (v<<5)
    uint32_t offA[2];
    #pragma unroll
    for (int mi = 0; mi < 2; mi++)
        offA[mi] = swz((m_w + mi * 16 + (lane & 15)) * 128 + (lane >> 4) * 16);
    uint32_t offB[4];
    #pragma unroll
    for (int ks = 0; ks < 4; ks++)
        offB[ks] = (uint32_t)(A_TILE + warp_n * 8192 +
                   swz((ks * 16 + (lane & 15)) * 128 + (lane >> 4) * 16));

    float c[2][8][4];
    #pragma unroll
    for (int mi = 0; mi < 2; mi++)
        #pragma unroll
        for (int nj = 0; nj < 8; nj++)
            #pragma unroll
            for (int q = 0; q < 4; q++) c[mi][nj][q] = 0.0f;

    // stage loader: 8 cp16 with register addressing only
    auto load_stage = [&](int ch, int st) {
        uint32_t dst = sbase + st * STAGE_BYTES;
        const char* Ax = Axh + ch * 128;                    // ch*64 halves
        #pragma unroll
        for (int q = 0; q < 4; q++)
            cp16(dst + sdstA + q * 4096, Ax + arow[q]);
        const unsigned char* Bs = Bbase + (size_t)ch * B_TILE + tid * 16;
        uint32_t bd = dst + A_TILE + tid * 16;
        #pragma unroll
        for (int q = 0; q < 4; q++)
            cp16(bd + q * 4096, Bs + q * 4096);
    };

    // prologue: stages 0..STG-2
    #pragma unroll
    for (int s = 0; s < STG - 1; s++) { load_stage(s, s); cp_commit(); }

    int st = 0;
    for (int i = 0; i < NCH; i++) {
        cp_wait<STG - 2>();
        __syncthreads();

        // Issue next chunk's copy BEFORE computing (target stage was consumed
        // in iteration i-1; the barrier above proves all threads are done).
        if (i + STG - 1 < NCH) {
            int nst = st + STG - 1; if (nst >= STG) nst -= STG;
            load_stage(i + STG - 1, nst);
        }
        cp_commit();

        uint32_t sb = sbase + st * STAGE_BYTES;
        #pragma unroll
        for (int ks = 0; ks < 4; ks++) {
            uint32_t a[2][4], bf[4][4];
            ldsm_x4(a[0], sb + (offA[0] ^ (ks << 5)));
            ldsm_x4(a[1], sb + (offA[1] ^ (ks << 5)));
            #pragma unroll
            for (int p = 0; p < 4; p++) ldsm_x4_t(bf[p], sb + (offB[ks] ^ (p << 5)));
            #pragma unroll
            for (int mi = 0; mi < 2; mi++)
                #pragma unroll
                for (int p = 0; p < 4; p++) {
                    mma16816(c[mi][2 * p],     a[mi], bf[p][0], bf[p][1]);
                    mma16816(c[mi][2 * p + 1], a[mi], bf[p][2], bf[p][3]);
                }
        }
        if (++st == STG) st = 0;
    }

    // -------- epilogue: (c + bias) * inv, red.v2 scatter-add by token --------
    float bi = bias[e];
    #pragma unroll
    for (int mi = 0; mi < 2; mi++) {
        #pragma unroll
        for (int r = 0; r < 2; r++) {
            int mrow = m_w + mi * 16 + r * 8 + (lane >> 2);
            int gm   = mt * 128 + mrow;
            int tok  = stok[mrow];
            float inv = g_inv[(size_t)be * KK + gm];
            float* orow = out + ((size_t)b * SS + tok) * OO + nt * 128 + n_w + (lane & 3) * 2;
            #pragma unroll
            for (int nj = 0; nj < 8; nj++)
                red2(&orow[nj * 8],
                     (c[mi][nj][r * 2]     + bi) * inv,
                     (c[mi][nj][r * 2 + 1] + bi) * inv);
        }
    }
}

// ============================================================================
// Launch: prep(1) -> topk(2) -> gemm(3)
// ============================================================================
extern "C" void kernel_launch(void* const* d_in, const int* in_sizes, int n_in,
                              void* d_out, int out_size)
{
    const float* x   = (const float*)d_in[0];   // [B,S,D]
    const float* gw  = (const float*)d_in[1];   // [D,E]
    const float* gb  = (const float*)d_in[2];   // [E]
    const float* w   = (const float*)d_in[3];   // [E,D,O]
    const float* bia = (const float*)d_in[4];   // [E,1]
    float* out = (float*)d_out;
    (void)in_sizes; (void)n_in; (void)out_size;

    cudaFuncSetAttribute(gemm_kernel, cudaFuncAttributeMaxDynamicSharedMemorySize, SMEM_DYN);

    prep_kernel<<<GATE_BLOCKS + WCONV_BLOCKS, 256>>>(x, gw, gb, w, out);
    topk_kernel<<<BB * EE, 1024>>>();
    {
        dim3 grid(OO / BN, KK / BM, BB * EE);   // (8, 4, 64)
        gemm_kernel<<<grid, 256, SMEM_DYN>>>(bia, out);
    }
}